// round 1
// baseline (speedup 1.0000x reference)
#include <cuda_runtime.h>
#include <math.h>

#define N_NODES 100000
#define N_EDGES 3200000
#define F_IN    48
#define F_HID   16

// ---------------- static device scratch (no allocations allowed) ----------------
__device__ int   g_is64;
__device__ int   g_src[N_EDGES];
__device__ int   g_dst[N_EDGES];
__device__ float g_wn [N_EDGES];
__device__ int   g_deg [N_NODES];
__device__ float g_dinv[N_NODES];
__device__ float g_xw[N_NODES * F_HID];  // per-layer x@W (gather source)
__device__ float g_h [N_NODES * F_HID];  // accumulator / layer output

// ---------------- helpers ----------------
__device__ __forceinline__ void red4(float* p, float a, float b, float c, float d) {
    asm volatile("red.global.add.v4.f32 [%0], {%1,%2,%3,%4};"
                 :: "l"(p), "f"(a), "f"(b), "f"(c), "f"(d) : "memory");
}

// ---------------- kernels ----------------
__global__ void k_zero_deg() {
    int i = blockIdx.x * blockDim.x + threadIdx.x;
    if (i < N_NODES) g_deg[i] = 0;
}

// Detect whether edge_index is int64 or int32. If the buffer holds int32 data,
// reading it as int64 yields values >= 2^32 (second random index in the high
// word) which are out of [0, N_NODES). 32 consecutive in-range int64 samples
// => genuinely int64.
__global__ void k_detect(const long long* p) {
    int ok = 1;
    for (int i = 0; i < 32; ++i) {
        long long v = p[i];
        if (v < 0 || v >= (long long)N_NODES) { ok = 0; break; }
    }
    g_is64 = ok;
}

__global__ void k_prep(const void* ei) {
    int e = blockIdx.x * blockDim.x + threadIdx.x;
    if (e >= N_EDGES) return;
    int s, d;
    if (g_is64) {
        const long long* p = (const long long*)ei;
        s = (int)p[e];
        d = (int)p[N_EDGES + e];
    } else {
        const int* p = (const int*)ei;
        s = p[e];
        d = p[N_EDGES + e];
    }
    g_src[e] = s;
    g_dst[e] = d;
    atomicAdd(&g_deg[d], 1);
}

__global__ void k_dinv() {
    int i = blockIdx.x * blockDim.x + threadIdx.x;
    if (i < N_NODES) g_dinv[i] = rsqrtf((float)(g_deg[i] + 1));  // +1 self loop
}

__global__ void k_norm() {
    int e = blockIdx.x * blockDim.x + threadIdx.x;
    if (e >= N_EDGES) return;
    g_wn[e] = g_dinv[g_src[e]] * g_dinv[g_dst[e]];
}

// Layer 1: xw = x @ W1 ; h_init = dinv^2 * xw + b1
// 16 threads per node (one per output feature). Grid is exact (N*16 % 256 == 0).
__global__ void k_xw_first(const float* __restrict__ x,
                           const float* __restrict__ W,
                           const float* __restrict__ b) {
    __shared__ float Ws[F_IN * F_HID];
    for (int i = threadIdx.x; i < F_IN * F_HID; i += blockDim.x) Ws[i] = W[i];
    __syncthreads();

    int gt   = blockIdx.x * blockDim.x + threadIdx.x;
    int node = gt >> 4;
    int f    = gt & 15;
    if (node >= N_NODES) return;

    const float* xr = x + node * F_IN;
    float acc = 0.f;
#pragma unroll
    for (int k = 0; k < F_IN; ++k) acc = fmaf(xr[k], Ws[k * F_HID + f], acc);

    float di = g_dinv[node];
    g_xw[node * F_HID + f] = acc;
    g_h [node * F_HID + f] = di * di * acc + __ldg(&b[f]);
}

// Layers 2-4: xw = relu(h) @ W ; h re-init = dinv^2 * xw + b
// Reads and rewrites g_h in place; each node row is touched only by 16 threads
// of one warp, ordered with __syncwarp().
__global__ void k_xw(const float* __restrict__ W,
                     const float* __restrict__ b) {
    __shared__ float Ws[F_HID * F_HID];
    for (int i = threadIdx.x; i < F_HID * F_HID; i += blockDim.x) Ws[i] = W[i];
    __syncthreads();

    int gt   = blockIdx.x * blockDim.x + threadIdx.x;
    int node = gt >> 4;
    int f    = gt & 15;
    if (node >= N_NODES) return;

    const float* hr = g_h + node * F_HID;
    float h[F_HID];
#pragma unroll
    for (int k = 0; k < F_HID; ++k) h[k] = fmaxf(hr[k], 0.f);
    __syncwarp();

    float acc = 0.f;
#pragma unroll
    for (int k = 0; k < F_HID; ++k) acc = fmaf(h[k], Ws[k * F_HID + f], acc);

    float di = g_dinv[node];
    g_xw[node * F_HID + f] = acc;
    g_h [node * F_HID + f] = di * di * acc + __ldg(&b[f]);
}

// Edge scatter: h[dst] += norm * xw[src], 4x red.v4.f32 per edge.
__global__ void k_scatter() {
    int e = blockIdx.x * blockDim.x + threadIdx.x;
    if (e >= N_EDGES) return;
    int   s = g_src[e];
    int   d = g_dst[e];
    float w = g_wn[e];
    const float4* sp = (const float4*)(g_xw + s * F_HID);
    float4 v0 = sp[0], v1 = sp[1], v2 = sp[2], v3 = sp[3];
    float* dp = g_h + d * F_HID;
    red4(dp +  0, w * v0.x, w * v0.y, w * v0.z, w * v0.w);
    red4(dp +  4, w * v1.x, w * v1.y, w * v1.z, w * v1.w);
    red4(dp +  8, w * v2.x, w * v2.y, w * v2.z, w * v2.w);
    red4(dp + 12, w * v3.x, w * v3.y, w * v3.z, w * v3.w);
}

// Final: sigmoid(h4 @ fc_w + fc_b)
__global__ void k_fc(const float* __restrict__ fcw,
                     const float* __restrict__ fcb,
                     float* __restrict__ out) {
    int i = blockIdx.x * blockDim.x + threadIdx.x;
    if (i >= N_NODES) return;
    const float* hr = g_h + i * F_HID;
    float acc = 0.f;
#pragma unroll
    for (int k = 0; k < F_HID; ++k) acc = fmaf(hr[k], __ldg(&fcw[k]), acc);
    acc += __ldg(&fcb[0]);
    out[i] = 1.f / (1.f + expf(-acc));
}

// ---------------- launch ----------------
extern "C" void kernel_launch(void* const* d_in, const int* in_sizes, int n_in,
                              void* d_out, int out_size) {
    const float* x    = (const float*)d_in[0];
    const void*  ei   = d_in[1];
    const float* W1   = (const float*)d_in[2];
    const float* b1   = (const float*)d_in[3];
    const float* W2   = (const float*)d_in[4];
    const float* b2   = (const float*)d_in[5];
    const float* W3   = (const float*)d_in[6];
    const float* b3   = (const float*)d_in[7];
    const float* W4   = (const float*)d_in[8];
    const float* b4   = (const float*)d_in[9];
    const float* fcw  = (const float*)d_in[10];
    const float* fcb  = (const float*)d_in[11];
    float* out = (float*)d_out;

    const int TB = 256;
    const int nodeBlocks = (N_NODES + TB - 1) / TB;          // 391
    const int edgeBlocks = (N_EDGES + TB - 1) / TB;          // 12500
    const int featBlocks = (N_NODES * F_HID + TB - 1) / TB;  // 6250

    // graph prep (amortized across layers)
    k_zero_deg<<<nodeBlocks, TB>>>();
    k_detect<<<1, 1>>>((const long long*)ei);
    k_prep<<<edgeBlocks, TB>>>(ei);
    k_dinv<<<nodeBlocks, TB>>>();
    k_norm<<<edgeBlocks, TB>>>();

    // layer 1
    k_xw_first<<<featBlocks, TB>>>(x, W1, b1);
    k_scatter<<<edgeBlocks, TB>>>();
    // layer 2
    k_xw<<<featBlocks, TB>>>(W2, b2);
    k_scatter<<<edgeBlocks, TB>>>();
    // layer 3
    k_xw<<<featBlocks, TB>>>(W3, b3);
    k_scatter<<<edgeBlocks, TB>>>();
    // layer 4
    k_xw<<<featBlocks, TB>>>(W4, b4);
    k_scatter<<<edgeBlocks, TB>>>();

    // readout
    k_fc<<<nodeBlocks, TB>>>(fcw, fcb, out);
}

// round 2
// speedup vs baseline: 1.7077x; 1.7077x over previous
#include <cuda_runtime.h>
#include <math.h>

#define N_NODES 100000
#define N_EDGES 3200000
#define F_IN    48
#define F_HID   16
#define TB      256
#define SCAN1_BLOCKS ((N_NODES + TB - 1) / TB)   // 391

// ---------------- static device scratch (no allocations allowed) ----------------
__device__ int   g_is64;
__device__ int   g_deg   [N_NODES];
__device__ float g_dinv  [N_NODES];
__device__ int   g_rowptr[N_NODES + 1];
__device__ int   g_cursor[N_NODES];
__device__ int   g_part  [512];          // block partial sums for scan
__device__ int   g_csrc  [N_EDGES];      // CSR (by dst): source node per slot
__device__ float g_cwn   [N_EDGES];      // CSR: edge norm per slot
__device__ float g_xwA   [N_NODES * F_HID];
__device__ float g_xwB   [N_NODES * F_HID];

// ---------------- prep kernels ----------------
__global__ void k_detect(const long long* p) {
    int ok = 1;
    for (int i = 0; i < 32; ++i) {
        long long v = p[i];
        if (v < 0 || v >= (long long)N_NODES) { ok = 0; break; }
    }
    g_is64 = ok;
}

__global__ void k_zero_deg() {
    int i = blockIdx.x * blockDim.x + threadIdx.x;
    if (i < N_NODES) g_deg[i] = 0;
}

// count in-degree (edges only; self-loop added in dinv)
__global__ void k_deg(const void* ei) {
    int e = blockIdx.x * blockDim.x + threadIdx.x;   // exact grid
    int d;
    if (g_is64) d = (int)((const long long*)ei)[N_EDGES + e];
    else        d = ((const int*)ei)[N_EDGES + e];
    atomicAdd(&g_deg[d], 1);
}

__global__ void k_dinv() {
    int i = blockIdx.x * blockDim.x + threadIdx.x;
    if (i < N_NODES) g_dinv[i] = rsqrtf((float)(g_deg[i] + 1));
}

// exclusive scan of deg -> rowptr (3 stages)
__global__ void k_scan1() {
    __shared__ int s[TB];
    int i = blockIdx.x * TB + threadIdx.x;
    int v = (i < N_NODES) ? g_deg[i] : 0;
    s[threadIdx.x] = v;
    __syncthreads();
    for (int off = 1; off < TB; off <<= 1) {
        int t = (threadIdx.x >= off) ? s[threadIdx.x - off] : 0;
        __syncthreads();
        s[threadIdx.x] += t;
        __syncthreads();
    }
    if (i < N_NODES) g_rowptr[i] = s[threadIdx.x] - v;   // local exclusive
    if (threadIdx.x == TB - 1) g_part[blockIdx.x] = s[TB - 1];
}

__global__ void k_scan2() {   // 1 block, 512 threads
    __shared__ int s[512];
    int t = threadIdx.x;
    int v = (t < SCAN1_BLOCKS) ? g_part[t] : 0;
    s[t] = v;
    __syncthreads();
    for (int off = 1; off < 512; off <<= 1) {
        int q = (t >= off) ? s[t - off] : 0;
        __syncthreads();
        s[t] += q;
        __syncthreads();
    }
    if (t < SCAN1_BLOCKS) g_part[t] = s[t] - v;          // exclusive
}

__global__ void k_scan3() {
    int i = blockIdx.x * TB + threadIdx.x;
    if (i < N_NODES) {
        int r = g_rowptr[i] + g_part[blockIdx.x];
        g_rowptr[i] = r;
        g_cursor[i] = r;
    }
    if (i == 0) g_rowptr[N_NODES] = N_EDGES;
}

// fill CSR: slot per edge via atomic cursor; norm = dinv[s]*dinv[d]
__global__ void k_fill(const void* ei) {
    int e = blockIdx.x * blockDim.x + threadIdx.x;   // exact grid
    int s, d;
    if (g_is64) {
        const long long* p = (const long long*)ei;
        s = (int)p[e]; d = (int)p[N_EDGES + e];
    } else {
        const int* p = (const int*)ei;
        s = p[e]; d = p[N_EDGES + e];
    }
    int pos = atomicAdd(&g_cursor[d], 1);
    g_csrc[pos] = s;
    g_cwn[pos]  = g_dinv[s] * g_dinv[d];
}

// ---------------- layer kernels ----------------
// xw1 = x @ W1. 16 threads/node (exact grid: N*16 % 256 == 0).
__global__ void k_xw_first(const float* __restrict__ x,
                           const float* __restrict__ W) {
    __shared__ float Ws[F_IN * F_HID];
    for (int i = threadIdx.x; i < F_IN * F_HID; i += blockDim.x) Ws[i] = W[i];
    __syncthreads();
    int gt   = blockIdx.x * blockDim.x + threadIdx.x;
    int node = gt >> 4;
    int f    = gt & 15;
    const float* xr = x + node * F_IN;
    float acc = 0.f;
#pragma unroll
    for (int k = 0; k < F_IN; ++k) acc = fmaf(xr[k], Ws[k * F_HID + f], acc);
    g_xwA[node * F_HID + f] = acc;
}

// Fused: h = CSR-gather(xin) + dinv^2*xin_self + b ; relu ; xout = h @ Wnext
// (16x16 GEMM done in-register via half-warp shuffles)
__global__ void k_layer(const float* __restrict__ b,
                        const float* __restrict__ Wn,
                        const float* __restrict__ xin,
                        float* __restrict__ xout) {
    __shared__ float Ws[F_HID * F_HID];
    for (int i = threadIdx.x; i < F_HID * F_HID; i += blockDim.x) Ws[i] = Wn[i];
    __syncthreads();

    int gt   = blockIdx.x * blockDim.x + threadIdx.x;
    int node = gt >> 4;
    int f    = gt & 15;

    int beg = g_rowptr[node];
    int end = g_rowptr[node + 1];
    float acc = 0.f;
    int j = beg;
    for (; j + 4 <= end; j += 4) {
        int   s0 = g_csrc[j],   s1 = g_csrc[j+1], s2 = g_csrc[j+2], s3 = g_csrc[j+3];
        float w0 = g_cwn[j],    w1 = g_cwn[j+1],  w2 = g_cwn[j+2],  w3 = g_cwn[j+3];
        acc = fmaf(w0, xin[s0 * F_HID + f], acc);
        acc = fmaf(w1, xin[s1 * F_HID + f], acc);
        acc = fmaf(w2, xin[s2 * F_HID + f], acc);
        acc = fmaf(w3, xin[s3 * F_HID + f], acc);
    }
    for (; j < end; ++j)
        acc = fmaf(g_cwn[j], xin[g_csrc[j] * F_HID + f], acc);

    float di = g_dinv[node];
    acc = fmaf(di * di, xin[node * F_HID + f], acc) + __ldg(&b[f]);

    float h = fmaxf(acc, 0.f);   // relu (layers 1-3)
    float o = 0.f;
#pragma unroll
    for (int k = 0; k < F_HID; ++k)
        o = fmaf(__shfl_sync(0xffffffffu, h, k, 16), Ws[k * F_HID + f], o);
    xout[node * F_HID + f] = o;
}

// Final layer: h4 = gather + self + b4 (no relu) ; out = sigmoid(h4 . fcw + fcb)
__global__ void k_final(const float* __restrict__ b,
                        const float* __restrict__ fcw,
                        const float* __restrict__ fcb,
                        const float* __restrict__ xin,
                        float* __restrict__ out) {
    int gt   = blockIdx.x * blockDim.x + threadIdx.x;
    int node = gt >> 4;
    int f    = gt & 15;

    int beg = g_rowptr[node];
    int end = g_rowptr[node + 1];
    float acc = 0.f;
    int j = beg;
    for (; j + 4 <= end; j += 4) {
        int   s0 = g_csrc[j],   s1 = g_csrc[j+1], s2 = g_csrc[j+2], s3 = g_csrc[j+3];
        float w0 = g_cwn[j],    w1 = g_cwn[j+1],  w2 = g_cwn[j+2],  w3 = g_cwn[j+3];
        acc = fmaf(w0, xin[s0 * F_HID + f], acc);
        acc = fmaf(w1, xin[s1 * F_HID + f], acc);
        acc = fmaf(w2, xin[s2 * F_HID + f], acc);
        acc = fmaf(w3, xin[s3 * F_HID + f], acc);
    }
    for (; j < end; ++j)
        acc = fmaf(g_cwn[j], xin[g_csrc[j] * F_HID + f], acc);

    float di = g_dinv[node];
    acc = fmaf(di * di, xin[node * F_HID + f], acc) + __ldg(&b[f]);

    float p = acc * __ldg(&fcw[f]);
#pragma unroll
    for (int o = 8; o > 0; o >>= 1) p += __shfl_xor_sync(0xffffffffu, p, o, 16);
    if (f == 0) out[node] = 1.f / (1.f + expf(-(p + __ldg(&fcb[0]))));
}

// ---------------- launch ----------------
extern "C" void kernel_launch(void* const* d_in, const int* in_sizes, int n_in,
                              void* d_out, int out_size) {
    const float* x   = (const float*)d_in[0];
    const void*  ei  = d_in[1];
    const float* W1  = (const float*)d_in[2];
    const float* b1  = (const float*)d_in[3];
    const float* W2  = (const float*)d_in[4];
    const float* b2  = (const float*)d_in[5];
    const float* W3  = (const float*)d_in[6];
    const float* b3  = (const float*)d_in[7];
    const float* W4  = (const float*)d_in[8];
    const float* b4  = (const float*)d_in[9];
    const float* fcw = (const float*)d_in[10];
    const float* fcb = (const float*)d_in[11];
    float* out = (float*)d_out;

    float *xwA, *xwB;
    cudaGetSymbolAddress((void**)&xwA, g_xwA);
    cudaGetSymbolAddress((void**)&xwB, g_xwB);

    const int nodeBlocks = SCAN1_BLOCKS;                     // 391
    const int edgeBlocks = N_EDGES / TB;                     // 12500 (exact)
    const int featBlocks = (N_NODES * F_HID) / TB;           // 6250  (exact)

    // ---- per-call graph prep (CSR by dst) ----
    k_detect<<<1, 1>>>((const long long*)ei);
    k_zero_deg<<<nodeBlocks, TB>>>();
    k_deg<<<edgeBlocks, TB>>>(ei);
    k_dinv<<<nodeBlocks, TB>>>();
    k_scan1<<<SCAN1_BLOCKS, TB>>>();
    k_scan2<<<1, 512>>>();
    k_scan3<<<SCAN1_BLOCKS, TB>>>();
    k_fill<<<edgeBlocks, TB>>>(ei);

    // ---- layers ----
    k_xw_first<<<featBlocks, TB>>>(x, W1);                   // xwA = x@W1
    k_layer<<<featBlocks, TB>>>(b1, W2, xwA, xwB);           // xwB = relu(h1)@W2
    k_layer<<<featBlocks, TB>>>(b2, W3, xwB, xwA);           // xwA = relu(h2)@W3
    k_layer<<<featBlocks, TB>>>(b3, W4, xwA, xwB);           // xwB = relu(h3)@W4
    k_final<<<featBlocks, TB>>>(b4, fcw, fcb, xwB, out);     // sigmoid(h4@fc)
}

// round 5
// speedup vs baseline: 2.1450x; 1.2560x over previous
#include <cuda_runtime.h>
#include <math.h>

#define N_NODES 100000
#define N_EDGES 3200000
#define F_IN    48
#define F_HID   16
#define TB      256
#define SCAN1_BLOCKS ((N_NODES + TB - 1) / TB)   // 391

// ---------------- static device scratch ----------------
__device__ int    g_is64;
__device__ int    g_deg   [N_NODES];
__device__ float  g_dinv  [N_NODES];
__device__ int    g_rowptr[N_NODES + 1];
__device__ int    g_cursor[N_NODES];
__device__ int    g_part  [512];
__device__ int2   g_epack [N_EDGES];       // packed (src,dst) int32
__device__ int    g_csrc  [N_EDGES];       // CSR by dst: src per slot
__device__ float  g_yA    [N_NODES * F_HID];
__device__ float  g_yB    [N_NODES * F_HID];
__device__ float  g_z     [N_NODES];       // scalar field for final layer

// ---------------- prep ----------------
__global__ void k_detect(const long long* p) {
    int ok = 1;
    for (int i = 0; i < 32; ++i) {
        long long v = p[i];
        if (v < 0 || v >= (long long)N_NODES) { ok = 0; break; }
    }
    g_is64 = ok;
}

// read edge_index once, pack to int2, count in-degree
__global__ void k_deg_pack(const void* ei) {
    int e = blockIdx.x * blockDim.x + threadIdx.x;   // exact grid
    int s, d;
    if (g_is64) {
        const long long* p = (const long long*)ei;
        s = (int)p[e]; d = (int)p[N_EDGES + e];
    } else {
        const int* p = (const int*)ei;
        s = p[e]; d = p[N_EDGES + e];
    }
    g_epack[e] = make_int2(s, d);
    atomicAdd(&g_deg[d], 1);
}

// exclusive scan of deg -> rowptr (3 stages); dinv fused into stage 1
__global__ void k_scan1() {
    __shared__ int s[TB];
    int i = blockIdx.x * TB + threadIdx.x;
    int v = (i < N_NODES) ? g_deg[i] : 0;
    if (i < N_NODES) g_dinv[i] = rsqrtf((float)(v + 1));
    s[threadIdx.x] = v;
    __syncthreads();
    for (int off = 1; off < TB; off <<= 1) {
        int t = (threadIdx.x >= off) ? s[threadIdx.x - off] : 0;
        __syncthreads();
        s[threadIdx.x] += t;
        __syncthreads();
    }
    if (i < N_NODES) g_rowptr[i] = s[threadIdx.x] - v;
    if (threadIdx.x == TB - 1) g_part[blockIdx.x] = s[TB - 1];
}

__global__ void k_scan2() {   // 1 block, 512 threads
    __shared__ int s[512];
    int t = threadIdx.x;
    int v = (t < SCAN1_BLOCKS) ? g_part[t] : 0;
    s[t] = v;
    __syncthreads();
    for (int off = 1; off < 512; off <<= 1) {
        int q = (t >= off) ? s[t - off] : 0;
        __syncthreads();
        s[t] += q;
        __syncthreads();
    }
    if (t < SCAN1_BLOCKS) g_part[t] = s[t] - v;
}

__global__ void k_scan3() {
    int i = blockIdx.x * TB + threadIdx.x;
    if (i < N_NODES) {
        int r = g_rowptr[i] + g_part[blockIdx.x];
        g_rowptr[i] = r;
        g_cursor[i] = r;
    }
    if (i == 0) g_rowptr[N_NODES] = N_EDGES;
}

__global__ void k_fill() {
    int e = blockIdx.x * blockDim.x + threadIdx.x;   // exact grid
    int2 sd = g_epack[e];
    int pos = atomicAdd(&g_cursor[sd.y], 1);
    g_csrc[pos] = sd.x;
}

// ---------------- layers ----------------
// y1 = dinv * (x @ W1); 16 threads/node, exact grid (no divergence here,
// but use the half-warp mask uniformly).
__global__ void k_xw_first(const float* __restrict__ x,
                           const float* __restrict__ W) {
    __shared__ float Ws[F_IN * F_HID];
    for (int i = threadIdx.x; i < F_IN * F_HID; i += blockDim.x) Ws[i] = W[i];
    __syncthreads();
    int gt   = blockIdx.x * blockDim.x + threadIdx.x;
    int node = gt >> 4;
    int f    = gt & 15;
    const unsigned hm = 0xffffu << (threadIdx.x & 16);
    const float* xr = x + node * F_IN;
    float x0 = xr[f], x1 = xr[f + 16], x2 = xr[f + 32];
    float acc = 0.f;
#pragma unroll
    for (int k = 0; k < 16; ++k)
        acc = fmaf(__shfl_sync(hm, x0, k, 16), Ws[k * F_HID + f], acc);
#pragma unroll
    for (int k = 0; k < 16; ++k)
        acc = fmaf(__shfl_sync(hm, x1, k, 16), Ws[(16 + k) * F_HID + f], acc);
#pragma unroll
    for (int k = 0; k < 16; ++k)
        acc = fmaf(__shfl_sync(hm, x2, k, 16), Ws[(32 + k) * F_HID + f], acc);
    g_yA[node * F_HID + f] = g_dinv[node] * acc;
}

// agg = sum(yin[neighbors]) + yin[self]; h = relu(dinv*agg + b);
// yout = dinv * (h @ W). 16 threads/node. All intra-loop shuffles use the
// half-warp mask: the 16 lanes of one node share identical control flow,
// the other half-warp (different node, different degree) does not.
__global__ void k_layer(const float* __restrict__ b,
                        const float* __restrict__ W,
                        const float* __restrict__ yin,
                        float* __restrict__ yout) {
    __shared__ float Ws[F_HID * F_HID];
    for (int i = threadIdx.x; i < F_HID * F_HID; i += blockDim.x) Ws[i] = W[i];
    __syncthreads();

    int gt   = blockIdx.x * blockDim.x + threadIdx.x;
    int node = gt >> 4;
    int f    = gt & 15;
    const unsigned hm = 0xffffu << (threadIdx.x & 16);

    int beg = g_rowptr[node];
    int end = g_rowptr[node + 1];
    float acc = yin[node * F_HID + f];                 // self
    int j = beg;
    for (; j + 16 <= end; j += 16) {
        int sv = g_csrc[j + f];                        // coalesced
#pragma unroll
        for (int k = 0; k < 16; ++k) {
            int s = __shfl_sync(hm, sv, k, 16);
            acc += yin[s * F_HID + f];
        }
    }
    for (; j < end; ++j)
        acc += yin[g_csrc[j] * F_HID + f];

    float di = g_dinv[node];
    float h  = fmaxf(fmaf(di, acc, __ldg(&b[f])), 0.f);
    float o  = 0.f;
#pragma unroll
    for (int k = 0; k < 16; ++k)
        o = fmaf(__shfl_sync(hm, h, k, 16), Ws[k * F_HID + f], o);
    yout[node * F_HID + f] = di * o;
}

// Layer 4 folded with FC direction: z = dinv * ((relu(h3) @ W4) . fcw)
__global__ void k_layer_z(const float* __restrict__ b,
                          const float* __restrict__ W,
                          const float* __restrict__ fcw,
                          const float* __restrict__ yin) {
    __shared__ float Ws[F_HID * F_HID];
    for (int i = threadIdx.x; i < F_HID * F_HID; i += blockDim.x) Ws[i] = W[i];
    __syncthreads();

    int gt   = blockIdx.x * blockDim.x + threadIdx.x;
    int node = gt >> 4;
    int f    = gt & 15;
    const unsigned hm = 0xffffu << (threadIdx.x & 16);

    int beg = g_rowptr[node];
    int end = g_rowptr[node + 1];
    float acc = yin[node * F_HID + f];
    int j = beg;
    for (; j + 16 <= end; j += 16) {
        int sv = g_csrc[j + f];
#pragma unroll
        for (int k = 0; k < 16; ++k) {
            int s = __shfl_sync(hm, sv, k, 16);
            acc += yin[s * F_HID + f];
        }
    }
    for (; j < end; ++j)
        acc += yin[g_csrc[j] * F_HID + f];

    float di = g_dinv[node];
    float h  = fmaxf(fmaf(di, acc, __ldg(&b[f])), 0.f);
    float o  = 0.f;
#pragma unroll
    for (int k = 0; k < 16; ++k)
        o = fmaf(__shfl_sync(hm, h, k, 16), Ws[k * F_HID + f], o);
    float p = o * __ldg(&fcw[f]);
#pragma unroll
    for (int off = 8; off > 0; off >>= 1) p += __shfl_xor_sync(hm, p, off, 16);
    if (f == 0) g_z[node] = di * p;
}

// Final: logit = dinv * (sum z[neighbors] + z[self]) + (b4.fcw + fcb); sigmoid.
// 16 lanes per node, strided over the edge list; reduction is post-loop
// (convergent) but still uses the half-warp mask.
__global__ void k_final(const float* __restrict__ b4,
                        const float* __restrict__ fcw,
                        const float* __restrict__ fcb,
                        float* __restrict__ out) {
    int gt   = blockIdx.x * blockDim.x + threadIdx.x;
    int node = gt >> 4;
    int f    = gt & 15;
    const unsigned hm = 0xffffu << (threadIdx.x & 16);

    int beg = g_rowptr[node];
    int end = g_rowptr[node + 1];
    float acc = 0.f;
    for (int j = beg + f; j < end; j += 16)
        acc += g_z[g_csrc[j]];
#pragma unroll
    for (int off = 8; off > 0; off >>= 1) acc += __shfl_xor_sync(hm, acc, off, 16);

    if (f == 0) {
        float C = __ldg(&fcb[0]);
#pragma unroll
        for (int k = 0; k < F_HID; ++k) C = fmaf(__ldg(&b4[k]), __ldg(&fcw[k]), C);
        float logit = fmaf(g_dinv[node], acc + g_z[node], C);
        out[node] = 1.f / (1.f + expf(-logit));
    }
}

// ---------------- launch ----------------
extern "C" void kernel_launch(void* const* d_in, const int* in_sizes, int n_in,
                              void* d_out, int out_size) {
    const float* x   = (const float*)d_in[0];
    const void*  ei  = d_in[1];
    const float* W1  = (const float*)d_in[2];
    const float* b1  = (const float*)d_in[3];
    const float* W2  = (const float*)d_in[4];
    const float* b2  = (const float*)d_in[5];
    const float* W3  = (const float*)d_in[6];
    const float* b3  = (const float*)d_in[7];
    const float* W4  = (const float*)d_in[8];
    const float* b4  = (const float*)d_in[9];
    const float* fcw = (const float*)d_in[10];
    const float* fcb = (const float*)d_in[11];
    float* out = (float*)d_out;

    float *yA, *yB;
    void* degp;
    cudaGetSymbolAddress((void**)&yA, g_yA);
    cudaGetSymbolAddress((void**)&yB, g_yB);
    cudaGetSymbolAddress(&degp, g_deg);

    const int edgeBlocks = N_EDGES / TB;             // 12500 (exact)
    const int featBlocks = (N_NODES * F_HID) / TB;   // 6250  (exact)

    // prep
    k_detect<<<1, 1>>>((const long long*)ei);
    cudaMemsetAsync(degp, 0, N_NODES * sizeof(int));
    k_deg_pack<<<edgeBlocks, TB>>>(ei);
    k_scan1<<<SCAN1_BLOCKS, TB>>>();
    k_scan2<<<1, 512>>>();
    k_scan3<<<SCAN1_BLOCKS, TB>>>();
    k_fill<<<edgeBlocks, TB>>>();

    // layers
    k_xw_first<<<featBlocks, TB>>>(x, W1);           // yA = dinv*(x@W1)
    k_layer  <<<featBlocks, TB>>>(b1, W2, yA, yB);   // yB
    k_layer  <<<featBlocks, TB>>>(b2, W3, yB, yA);   // yA
    k_layer_z<<<featBlocks, TB>>>(b3, W4, fcw, yA);  // g_z
    k_final  <<<featBlocks, TB>>>(b4, fcw, fcb, out);
}

// round 7
// speedup vs baseline: 2.1453x; 1.0001x over previous
#include <cuda_runtime.h>
#include <cuda_fp16.h>
#include <math.h>

#define N_NODES 100000
#define N_EDGES 3200000
#define F_IN    48
#define F_HID   16
#define TB      256
#define SCAN1_BLOCKS ((N_NODES + TB - 1) / TB)   // 391

// ---------------- static device scratch ----------------
__device__ int    g_is64;
__device__ int    g_deg   [N_NODES];
__device__ float  g_dinv  [N_NODES];
__device__ int    g_rowptr[N_NODES + 1];
__device__ int    g_cursor[N_NODES];
__device__ int    g_part  [512];
__device__ int2   g_epack [N_EDGES];       // packed (src,dst) int32
__device__ int    g_csrc  [N_EDGES];       // CSR by dst: src per slot
__device__ __half g_yA    [N_NODES * F_HID];
__device__ __half g_yB    [N_NODES * F_HID];
__device__ float  g_z     [N_NODES];       // scalar field for final layer

// ---------------- prep ----------------
__global__ void k_detect(const long long* p) {
    int ok = 1;
    for (int i = 0; i < 32; ++i) {
        long long v = p[i];
        if (v < 0 || v >= (long long)N_NODES) { ok = 0; break; }
    }
    g_is64 = ok;
}

// read edge_index once, pack to int2, count in-degree
__global__ void k_deg_pack(const void* ei) {
    int e = blockIdx.x * blockDim.x + threadIdx.x;   // exact grid
    int s, d;
    if (g_is64) {
        const long long* p = (const long long*)ei;
        s = (int)p[e]; d = (int)p[N_EDGES + e];
    } else {
        const int* p = (const int*)ei;
        s = p[e]; d = p[N_EDGES + e];
    }
    g_epack[e] = make_int2(s, d);
    atomicAdd(&g_deg[d], 1);
}

// exclusive scan of deg -> rowptr (3 stages); dinv fused into stage 1
__global__ void k_scan1() {
    __shared__ int s[TB];
    int i = blockIdx.x * TB + threadIdx.x;
    int v = (i < N_NODES) ? g_deg[i] : 0;
    if (i < N_NODES) g_dinv[i] = rsqrtf((float)(v + 1));
    s[threadIdx.x] = v;
    __syncthreads();
    for (int off = 1; off < TB; off <<= 1) {
        int t = (threadIdx.x >= off) ? s[threadIdx.x - off] : 0;
        __syncthreads();
        s[threadIdx.x] += t;
        __syncthreads();
    }
    if (i < N_NODES) g_rowptr[i] = s[threadIdx.x] - v;
    if (threadIdx.x == TB - 1) g_part[blockIdx.x] = s[TB - 1];
}

__global__ void k_scan2() {   // 1 block, 512 threads
    __shared__ int s[512];
    int t = threadIdx.x;
    int v = (t < SCAN1_BLOCKS) ? g_part[t] : 0;
    s[t] = v;
    __syncthreads();
    for (int off = 1; off < 512; off <<= 1) {
        int q = (t >= off) ? s[t - off] : 0;
        __syncthreads();
        s[t] += q;
        __syncthreads();
    }
    if (t < SCAN1_BLOCKS) g_part[t] = s[t] - v;
}

__global__ void k_scan3() {
    int i = blockIdx.x * TB + threadIdx.x;
    if (i < N_NODES) {
        int r = g_rowptr[i] + g_part[blockIdx.x];
        g_rowptr[i] = r;
        g_cursor[i] = r;
    }
    if (i == 0) g_rowptr[N_NODES] = N_EDGES;
}

__global__ void k_fill() {
    int e = blockIdx.x * blockDim.x + threadIdx.x;   // exact grid
    int2 sd = g_epack[e];
    int pos = atomicAdd(&g_cursor[sd.y], 1);
    g_csrc[pos] = sd.x;
}

// ---------------- layers ----------------
// y1 = half(dinv * (x @ W1)); 16 threads/node, exact grid
__global__ void k_xw_first(const float* __restrict__ x,
                           const float* __restrict__ W) {
    __shared__ float Ws[F_IN * F_HID];
    for (int i = threadIdx.x; i < F_IN * F_HID; i += blockDim.x) Ws[i] = W[i];
    __syncthreads();
    int gt   = blockIdx.x * blockDim.x + threadIdx.x;
    int node = gt >> 4;
    int f    = gt & 15;
    const unsigned hm = 0xffffu << (threadIdx.x & 16);
    const float* xr = x + node * F_IN;
    float x0 = xr[f], x1 = xr[f + 16], x2 = xr[f + 32];
    float acc = 0.f;
#pragma unroll
    for (int k = 0; k < 16; ++k)
        acc = fmaf(__shfl_sync(hm, x0, k, 16), Ws[k * F_HID + f], acc);
#pragma unroll
    for (int k = 0; k < 16; ++k)
        acc = fmaf(__shfl_sync(hm, x1, k, 16), Ws[(16 + k) * F_HID + f], acc);
#pragma unroll
    for (int k = 0; k < 16; ++k)
        acc = fmaf(__shfl_sync(hm, x2, k, 16), Ws[(32 + k) * F_HID + f], acc);
    g_yA[node * F_HID + f] = __float2half_rn(g_dinv[node] * acc);
}

// agg = sum(yin[neighbors]) + yin[self]; h = relu(dinv*agg + b);
// yout = half(dinv * (h @ W)). 16 threads/node. All intra-loop shuffles use
// the half-warp mask (lanes of one node share control flow; the other
// half-warp has a different degree).
__global__ void k_layer(const float* __restrict__ b,
                        const float* __restrict__ W,
                        const __half* __restrict__ yin,
                        __half* __restrict__ yout) {
    __shared__ float Ws[F_HID * F_HID];
    for (int i = threadIdx.x; i < F_HID * F_HID; i += blockDim.x) Ws[i] = W[i];
    __syncthreads();

    int gt   = blockIdx.x * blockDim.x + threadIdx.x;
    int node = gt >> 4;
    int f    = gt & 15;
    const unsigned hm = 0xffffu << (threadIdx.x & 16);

    int beg = g_rowptr[node];
    int end = g_rowptr[node + 1];
    float acc = __half2float(yin[node * F_HID + f]);   // self
    int j = beg;
    for (; j + 16 <= end; j += 16) {
        int sv = g_csrc[j + f];                        // coalesced
#pragma unroll
        for (int k = 0; k < 16; ++k) {
            int s = __shfl_sync(hm, sv, k, 16);
            acc += __half2float(yin[s * F_HID + f]);
        }
    }
    for (; j < end; ++j)
        acc += __half2float(yin[g_csrc[j] * F_HID + f]);

    float di = g_dinv[node];
    float h  = fmaxf(fmaf(di, acc, __ldg(&b[f])), 0.f);
    float o  = 0.f;
#pragma unroll
    for (int k = 0; k < 16; ++k)
        o = fmaf(__shfl_sync(hm, h, k, 16), Ws[k * F_HID + f], o);
    yout[node * F_HID + f] = __float2half_rn(di * o);
}

// Layer 4 folded with FC direction: z = dinv * ((relu(h3) @ W4) . fcw)
__global__ void k_layer_z(const float* __restrict__ b,
                          const float* __restrict__ W,
                          const float* __restrict__ fcw,
                          const __half* __restrict__ yin) {
    __shared__ float Ws[F_HID * F_HID];
    for (int i = threadIdx.x; i < F_HID * F_HID; i += blockDim.x) Ws[i] = W[i];
    __syncthreads();

    int gt   = blockIdx.x * blockDim.x + threadIdx.x;
    int node = gt >> 4;
    int f    = gt & 15;
    const unsigned hm = 0xffffu << (threadIdx.x & 16);

    int beg = g_rowptr[node];
    int end = g_rowptr[node + 1];
    float acc = __half2float(yin[node * F_HID + f]);
    int j = beg;
    for (; j + 16 <= end; j += 16) {
        int sv = g_csrc[j + f];
#pragma unroll
        for (int k = 0; k < 16; ++k) {
            int s = __shfl_sync(hm, sv, k, 16);
            acc += __half2float(yin[s * F_HID + f]);
        }
    }
    for (; j < end; ++j)
        acc += __half2float(yin[g_csrc[j] * F_HID + f]);

    float di = g_dinv[node];
    float h  = fmaxf(fmaf(di, acc, __ldg(&b[f])), 0.f);
    float o  = 0.f;
#pragma unroll
    for (int k = 0; k < 16; ++k)
        o = fmaf(__shfl_sync(hm, h, k, 16), Ws[k * F_HID + f], o);
    float p = o * __ldg(&fcw[f]);
#pragma unroll
    for (int off = 8; off > 0; off >>= 1) p += __shfl_xor_sync(hm, p, off, 16);
    if (f == 0) g_z[node] = di * p;
}

// Final: logit = dinv * (sum z[neighbors] + z[self]) + (b4.fcw + fcb); sigmoid.
__global__ void k_final(const float* __restrict__ b4,
                        const float* __restrict__ fcw,
                        const float* __restrict__ fcb,
                        float* __restrict__ out) {
    int gt   = blockIdx.x * blockDim.x + threadIdx.x;
    int node = gt >> 4;
    int f    = gt & 15;
    const unsigned hm = 0xffffu << (threadIdx.x & 16);

    int beg = g_rowptr[node];
    int end = g_rowptr[node + 1];
    float acc = 0.f;
    for (int j = beg + f; j < end; j += 16)
        acc += g_z[g_csrc[j]];
#pragma unroll
    for (int off = 8; off > 0; off >>= 1) acc += __shfl_xor_sync(hm, acc, off, 16);

    if (f == 0) {
        float C = __ldg(&fcb[0]);
#pragma unroll
        for (int k = 0; k < F_HID; ++k) C = fmaf(__ldg(&b4[k]), __ldg(&fcw[k]), C);
        float logit = fmaf(g_dinv[node], acc + g_z[node], C);
        out[node] = 1.f / (1.f + expf(-logit));
    }
}

// ---------------- launch ----------------
extern "C" void kernel_launch(void* const* d_in, const int* in_sizes, int n_in,
                              void* d_out, int out_size) {
    const float* x   = (const float*)d_in[0];
    const void*  ei  = d_in[1];
    const float* W1  = (const float*)d_in[2];
    const float* b1  = (const float*)d_in[3];
    const float* W2  = (const float*)d_in[4];
    const float* b2  = (const float*)d_in[5];
    const float* W3  = (const float*)d_in[6];
    const float* b3  = (const float*)d_in[7];
    const float* W4  = (const float*)d_in[8];
    const float* b4  = (const float*)d_in[9];
    const float* fcw = (const float*)d_in[10];
    const float* fcb = (const float*)d_in[11];
    float* out = (float*)d_out;

    __half *yA, *yB;
    void* degp;
    cudaGetSymbolAddress((void**)&yA, g_yA);
    cudaGetSymbolAddress((void**)&yB, g_yB);
    cudaGetSymbolAddress(&degp, g_deg);

    const int edgeBlocks = N_EDGES / TB;             // 12500 (exact)
    const int featBlocks = (N_NODES * F_HID) / TB;   // 6250  (exact)

    // prep
    k_detect<<<1, 1>>>((const long long*)ei);
    cudaMemsetAsync(degp, 0, N_NODES * sizeof(int));
    k_deg_pack<<<edgeBlocks, TB>>>(ei);
    k_scan1<<<SCAN1_BLOCKS, TB>>>();
    k_scan2<<<1, 512>>>();
    k_scan3<<<SCAN1_BLOCKS, TB>>>();
    k_fill<<<edgeBlocks, TB>>>();

    // layers
    k_xw_first<<<featBlocks, TB>>>(x, W1);           // yA = half(dinv*(x@W1))
    k_layer  <<<featBlocks, TB>>>(b1, W2, yA, yB);   // yB
    k_layer  <<<featBlocks, TB>>>(b2, W3, yB, yA);   // yA
    k_layer_z<<<featBlocks, TB>>>(b3, W4, fcw, yA);  // g_z (fp32)
    k_final  <<<featBlocks, TB>>>(b4, fcw, fcb, out);
}